// round 15
// baseline (speedup 1.0000x reference)
#include <cuda_runtime.h>
#include <cuda_bf16.h>
#include <cstdint>

// EdgeDecoder: probs = sigmoid(relu(relu(concat(emb[u],emb[v])@W1+b1)@W2+b2)@W3+b3)
// R15 hybrid: layer1 via per-node Pa/Pb FMA precompute (cheap: 100K nodes);
// edge kernel does ONLY layer2 on tensor cores (48 MMAs/warp-tile, was 96),
// 3-term bf16 hi/lo split, coalesced 512B/edge gather from L2-resident tables,
// R11 register epilogue (layer3 dot in C-frag layout + quad shfl reduction).

#define MAX_NODES 100000
#define EPB 128
#define APITCH_B 144     // A row pitch bytes (128B data + 16 pad) — conflict-free ldmatrix

__device__ float g_Pa[(size_t)MAX_NODES * 64];
__device__ float g_Pb[(size_t)MAX_NODES * 64];
// Per-lane packed W2 fragments: [kt(4)][nt(4)][lane(32)] -> uint2 (b0,b1)
__device__ __align__(16) uint2 g_W2fragHi[512];
__device__ __align__(16) uint2 g_W2fragLo[512];

__device__ __forceinline__ uint32_t smem_u32(const void* p) {
    uint32_t a;
    asm("{ .reg .u64 t; cvta.to.shared.u64 t, %1; cvt.u32.u64 %0, t; }" : "=r"(a) : "l"(p));
    return a;
}
__device__ __forceinline__ void ldmatrix_x4(uint32_t& a0, uint32_t& a1,
                                            uint32_t& a2, uint32_t& a3, uint32_t addr) {
    asm volatile("ldmatrix.sync.aligned.m8n8.x4.shared.b16 {%0,%1,%2,%3}, [%4];"
                 : "=r"(a0), "=r"(a1), "=r"(a2), "=r"(a3) : "r"(addr));
}
__device__ __forceinline__ void mma_bf16(float* c, uint32_t a0, uint32_t a1,
                                         uint32_t a2, uint32_t a3,
                                         uint32_t b0, uint32_t b1) {
    asm volatile("mma.sync.aligned.m16n8k16.row.col.f32.bf16.bf16.f32 "
                 "{%0,%1,%2,%3},{%4,%5,%6,%7},{%8,%9},{%0,%1,%2,%3};"
                 : "+f"(c[0]), "+f"(c[1]), "+f"(c[2]), "+f"(c[3])
                 : "r"(a0), "r"(a1), "r"(a2), "r"(a3), "r"(b0), "r"(b1));
}
__device__ __forceinline__ uint32_t pack_hi(float a, float b) {
    __nv_bfloat162 h = __floats2bfloat162_rn(a, b);
    return *(uint32_t*)&h;
}
__device__ __forceinline__ uint32_t pack_lo(float a, float b, uint32_t hi) {
    __nv_bfloat162 h = *(__nv_bfloat162*)&hi;
    __nv_bfloat162 l = __floats2bfloat162_rn(a - __bfloat162float(h.x),
                                             b - __bfloat162float(h.y));
    return *(uint32_t*)&l;
}

// ---------------- precompute (4-way split: node x {Pa,Pb} x col-half) ----------------
__global__ void __launch_bounds__(256)
precompute_kernel(const float* __restrict__ emb,
                  const float* __restrict__ W1,
                  const float* __restrict__ b1,
                  int n_nodes) {
    __shared__ float sW1[32 * 64];
    __shared__ float sb1[64];
    for (int i = threadIdx.x; i < 32 * 64; i += blockDim.x) sW1[i] = W1[i];
    if (threadIdx.x < 64) sb1[threadIdx.x] = b1[threadIdx.x];
    __syncthreads();

    int t = blockIdx.x * blockDim.x + threadIdx.x;
    int n = t >> 2;
    if (n >= n_nodes) return;
    int part = (t >> 1) & 1;          // 0 -> Pa (W1 rows 0..15, +b1), 1 -> Pb (rows 16..31)
    int ch   = t & 1;                 // output col half

    float x[16];
    const float4* e4 = (const float4*)(emb + (size_t)n * 16);
#pragma unroll
    for (int i = 0; i < 4; i++) {
        float4 v = e4[i];
        x[4 * i + 0] = v.x; x[4 * i + 1] = v.y;
        x[4 * i + 2] = v.z; x[4 * i + 3] = v.w;
    }

    const int j0 = ch * 32;
    const int kbase = part * 16;
    float acc[32];
#pragma unroll
    for (int j = 0; j < 32; j++) acc[j] = part ? 0.0f : sb1[j0 + j];
#pragma unroll
    for (int k = 0; k < 16; k++)
#pragma unroll
        for (int j = 0; j < 32; j++)
            acc[j] = fmaf(x[k], sW1[(kbase + k) * 64 + j0 + j], acc[j]);

    float* dst = (part ? g_Pb : g_Pa) + (size_t)n * 64 + j0;
    float4* d4 = (float4*)dst;
#pragma unroll
    for (int j4 = 0; j4 < 8; j4++)
        d4[j4] = make_float4(acc[4 * j4], acc[4 * j4 + 1], acc[4 * j4 + 2], acc[4 * j4 + 3]);
}

// ---------------- prep: per-lane packed W2 fragments (hi/lo split) ----------------
__global__ void __launch_bounds__(128)
prep_bfrag(const float* __restrict__ W2) {
    for (int e = threadIdx.x; e < 512; e += 128) {
        int lane = e & 31;
        int nt = (e >> 5) & 3;
        int kt = e >> 7;
        int n  = nt * 8 + (lane >> 2);
        int k0 = kt * 16 + (lane & 3) * 2;
        float w00 = W2[(k0 + 0) * 32 + n];
        float w01 = W2[(k0 + 1) * 32 + n];
        float w10 = W2[(k0 + 8) * 32 + n];
        float w11 = W2[(k0 + 9) * 32 + n];
        uint32_t h0 = pack_hi(w00, w01), h1 = pack_hi(w10, w11);
        g_W2fragHi[e] = make_uint2(h0, h1);
        g_W2fragLo[e] = make_uint2(pack_lo(w00, w01, h0), pack_lo(w10, w11, h1));
    }
}

// ---------------- edge kernel: gather Pa/Pb -> relu/split -> layer2 MMA -> epilogue ----------------
__global__ void __launch_bounds__(256, 4)
edge_kernel(const int* __restrict__ ei,
            const float* __restrict__ b2,
            const float* __restrict__ W3,
            const float* __restrict__ b3,
            float* __restrict__ out,
            int E, int do_idx) {
    __shared__ __align__(16) unsigned char sAhi[EPB * APITCH_B];
    __shared__ __align__(16) unsigned char sAlo[EPB * APITCH_B];
    __shared__ __align__(16) uint2 sW2H[512], sW2L[512];
    __shared__ int sU[EPB], sV[EPB];
    __shared__ __align__(16) float sB2[32], sW3[32];
    __shared__ float sB3;

    const int tid = threadIdx.x;
    const int wid = tid >> 5, lid = tid & 31;
    const int q = lid & 3;

    for (int i = tid; i < 512; i += 256) { sW2H[i] = g_W2fragHi[i]; sW2L[i] = g_W2fragLo[i]; }
    if (tid < 32) { sB2[tid] = b2[tid]; sW3[tid] = W3[tid]; }
    if (tid == 0) sB3 = b3[0];

    const int base = blockIdx.x * EPB;
    const int nE = min(EPB, E - base);
    if (tid < EPB) {
        if (tid < nE) { sU[tid] = __ldg(ei + base + tid); sV[tid] = __ldg(ei + (size_t)E + base + tid); }
        else          { sU[tid] = 0; sV[tid] = 0; }
    }
    __syncthreads();

    // Coalesced gather: 16 lanes cover one edge row (64 floats from Pa + Pb).
    // relu(Pa[u]+Pb[v]) -> bf16 hi/lo into A tiles.
#pragma unroll
    for (int i = 0; i < 8; i++) {
        int idx = i * 256 + tid;
        int le = idx >> 4;
        int s  = idx & 15;
        float4 a = __ldg((const float4*)(g_Pa + (size_t)sU[le] * 64) + s);
        float4 v = __ldg((const float4*)(g_Pb + (size_t)sV[le] * 64) + s);
        float x0 = fmaxf(a.x + v.x, 0.0f);
        float x1 = fmaxf(a.y + v.y, 0.0f);
        float x2 = fmaxf(a.z + v.z, 0.0f);
        float x3 = fmaxf(a.w + v.w, 0.0f);
        uint32_t h01 = pack_hi(x0, x1), h23 = pack_hi(x2, x3);
        uint32_t l01 = pack_lo(x0, x1, h01), l23 = pack_lo(x2, x3, h23);
        uint32_t off = (uint32_t)le * APITCH_B + (uint32_t)s * 8;
        *(uint2*)(sAhi + off) = make_uint2(h01, h23);
        *(uint2*)(sAlo + off) = make_uint2(l01, l23);
    }
    __syncthreads();

    // Layer2 GEMM: each of 8 warps computes 16 rows x 32 cols, K=64, 3-term split.
    float acc2[4][4];
#pragma unroll
    for (int nt = 0; nt < 4; nt++)
#pragma unroll
        for (int r = 0; r < 4; r++) acc2[nt][r] = 0.0f;

    const int r0 = wid * 16;
    const uint32_t abh = smem_u32(sAhi);
    const uint32_t abl = smem_u32(sAlo);
    const uint32_t rbase = ((uint32_t)r0 + (uint32_t)(lid & 15)) * APITCH_B + ((uint32_t)(lid >> 4)) * 16;

#pragma unroll
    for (int kt = 0; kt < 4; kt++) {
        uint32_t ah0, ah1, ah2, ah3, al0, al1, al2, al3;
        uint32_t rowoff = rbase + (uint32_t)kt * 32;
        ldmatrix_x4(ah0, ah1, ah2, ah3, abh + rowoff);
        ldmatrix_x4(al0, al1, al2, al3, abl + rowoff);
#pragma unroll
        for (int nt = 0; nt < 4; nt++) {
            uint2 bh = sW2H[(kt * 4 + nt) * 32 + lid];
            uint2 bl = sW2L[(kt * 4 + nt) * 32 + lid];
            mma_bf16(acc2[nt], ah0, ah1, ah2, ah3, bh.x, bh.y);
            mma_bf16(acc2[nt], al0, al1, al2, al3, bh.x, bh.y);
            mma_bf16(acc2[nt], ah0, ah1, ah2, ah3, bl.x, bl.y);
        }
    }

    // Register epilogue: layer3 dot in C-fragment layout + quad shfl reduction.
    float zA = 0.0f, zB = 0.0f;
#pragma unroll
    for (int nt = 0; nt < 4; nt++) {
        float2 bb = *(const float2*)(sB2 + nt * 8 + 2 * q);
        float2 ww = *(const float2*)(sW3 + nt * 8 + 2 * q);
        zA = fmaf(fmaxf(acc2[nt][0] + bb.x, 0.0f), ww.x, zA);
        zA = fmaf(fmaxf(acc2[nt][1] + bb.y, 0.0f), ww.y, zA);
        zB = fmaf(fmaxf(acc2[nt][2] + bb.x, 0.0f), ww.x, zB);
        zB = fmaf(fmaxf(acc2[nt][3] + bb.y, 0.0f), ww.y, zB);
    }
    zA += __shfl_xor_sync(0xffffffffu, zA, 1);
    zA += __shfl_xor_sync(0xffffffffu, zA, 2);
    zB += __shfl_xor_sync(0xffffffffu, zB, 1);
    zB += __shfl_xor_sync(0xffffffffu, zB, 2);
    if (q == 0) {
        int rA = r0 + (lid >> 2);
        int rB = rA + 8;
        if (rA < nE) out[base + rA] = 1.0f / (1.0f + __expf(-(zA + sB3)));
        if (rB < nE) out[base + rB] = 1.0f / (1.0f + __expf(-(zB + sB3)));
    }

    // edge_index passthrough (from staged indices, coalesced).
    if (do_idx) {
        if (tid < EPB) {
            if (tid < nE) out[(size_t)E + base + tid] = (float)sU[tid];
        } else {
            int t2 = tid - EPB;
            if (t2 < nE) out[(size_t)2 * E + base + t2] = (float)sV[t2];
        }
    }
}

extern "C" void kernel_launch(void* const* d_in, const int* in_sizes, int n_in,
                              void* d_out, int out_size) {
    const float* emb = (const float*)d_in[0];
    const int*   ei  = (const int*)d_in[1];
    const float* W1  = (const float*)d_in[2];
    const float* b1  = (const float*)d_in[3];
    const float* W2  = (const float*)d_in[4];
    const float* b2  = (const float*)d_in[5];
    const float* W3  = (const float*)d_in[6];
    const float* b3  = (const float*)d_in[7];

    int n_nodes = in_sizes[0] / 16;
    int E       = in_sizes[1] / 2;
    float* out  = (float*)d_out;
    int do_idx  = (out_size >= 3 * E) ? 1 : 0;

    precompute_kernel<<<(4 * n_nodes + 255) / 256, 256>>>(emb, W1, b1, n_nodes);
    prep_bfrag<<<1, 128>>>(W2);
    edge_kernel<<<(E + EPB - 1) / EPB, 256>>>(ei, b2, W3, b3, out, E, do_idx);
}

// round 16
// speedup vs baseline: 1.2531x; 1.2531x over previous
#include <cuda_runtime.h>
#include <cuda_bf16.h>
#include <cstdint>

// EdgeDecoder: probs = sigmoid(relu(relu(concat(emb[u],emb[v])@W1+b1)@W2+b2)@W3+b3)
// R10: fully fused tensor-core version (layer1 MMA -> in-register relu/resplit ->
//      layer2 MMA), 3-term bf16 hi/lo splits, raw-emb gather (128B/edge).
// R11: register epilogue (layer3 dot in C-frag layout + quad shfl reduction). BEST.
// R16: per-node emb bf16 hi/lo split PRECOMPUTED (edge-independent) — gather
//      becomes pure uint4 load/store; deletes ~24 cvt + 8 sub + 4 STS per
//      thread-tile from the edge kernel. Mainloop/epilogue identical to R11.

#define MAX_NODES 100000
#define EPB 128
#define APITCH 80        // A row pitch bytes (64B emb-pair data + 16 pad)

// Pre-split embeddings: [node*2 + half] -> 8 bf16 (16B). hi and lo tables.
__device__ __align__(16) uint4 g_EmbHi[(size_t)MAX_NODES * 2];
__device__ __align__(16) uint4 g_EmbLo[(size_t)MAX_NODES * 2];
// Per-lane packed fragments: W1 [kt1(2)][j(8)][lane], W2 [kt(4)][nt(4)][lane]
__device__ __align__(16) uint2 g_W1fragHi[512];
__device__ __align__(16) uint2 g_W1fragLo[512];
__device__ __align__(16) uint2 g_W2fragHi[512];
__device__ __align__(16) uint2 g_W2fragLo[512];

__device__ __forceinline__ uint32_t smem_u32(const void* p) {
    uint32_t a;
    asm("{ .reg .u64 t; cvta.to.shared.u64 t, %1; cvt.u32.u64 %0, t; }" : "=r"(a) : "l"(p));
    return a;
}
__device__ __forceinline__ void ldmatrix_x4(uint32_t& a0, uint32_t& a1,
                                            uint32_t& a2, uint32_t& a3, uint32_t addr) {
    asm volatile("ldmatrix.sync.aligned.m8n8.x4.shared.b16 {%0,%1,%2,%3}, [%4];"
                 : "=r"(a0), "=r"(a1), "=r"(a2), "=r"(a3) : "r"(addr));
}
__device__ __forceinline__ void mma_bf16(float* c, uint32_t a0, uint32_t a1,
                                         uint32_t a2, uint32_t a3,
                                         uint32_t b0, uint32_t b1) {
    asm volatile("mma.sync.aligned.m16n8k16.row.col.f32.bf16.bf16.f32 "
                 "{%0,%1,%2,%3},{%4,%5,%6,%7},{%8,%9},{%0,%1,%2,%3};"
                 : "+f"(c[0]), "+f"(c[1]), "+f"(c[2]), "+f"(c[3])
                 : "r"(a0), "r"(a1), "r"(a2), "r"(a3), "r"(b0), "r"(b1));
}
__device__ __forceinline__ uint32_t pack_hi(float a, float b) {
    __nv_bfloat162 h = __floats2bfloat162_rn(a, b);
    return *(uint32_t*)&h;
}
__device__ __forceinline__ uint32_t pack_lo(float a, float b, uint32_t hi) {
    __nv_bfloat162 h = *(__nv_bfloat162*)&hi;
    __nv_bfloat162 l = __floats2bfloat162_rn(a - __bfloat162float(h.x),
                                             b - __bfloat162float(h.y));
    return *(uint32_t*)&l;
}

// ---------------- prep: per-node emb bf16 hi/lo split ----------------
__global__ void __launch_bounds__(256)
prep_emb(const float* __restrict__ emb, int n_nodes) {
    int idx = blockIdx.x * blockDim.x + threadIdx.x;   // (node, half)
    if (idx >= n_nodes * 2) return;
    const float4* src = (const float4*)(emb + (size_t)(idx) * 8);
    float4 v0 = __ldg(src);
    float4 v1 = __ldg(src + 1);
    uint32_t h0 = pack_hi(v0.x, v0.y), h1 = pack_hi(v0.z, v0.w);
    uint32_t h2 = pack_hi(v1.x, v1.y), h3 = pack_hi(v1.z, v1.w);
    uint32_t l0 = pack_lo(v0.x, v0.y, h0), l1 = pack_lo(v0.z, v0.w, h1);
    uint32_t l2 = pack_lo(v1.x, v1.y, h2), l3 = pack_lo(v1.z, v1.w, h3);
    g_EmbHi[idx] = make_uint4(h0, h1, h2, h3);
    g_EmbLo[idx] = make_uint4(l0, l1, l2, l3);
}

// ---------------- prep: per-lane packed W1/W2 fragments (hi/lo split) ----------------
__global__ void __launch_bounds__(256)
prep_frags(const float* __restrict__ W1, const float* __restrict__ W2) {
    int tid = threadIdx.x;
    for (int e = tid; e < 512; e += 256) {
        int lane = e & 31;
        {   // W1 [32 x 64]: e = kt1*256 + j*32 + lane
            int kt1 = e >> 8, j = (e >> 5) & 7;
            int k0 = kt1 * 16 + (lane & 3) * 2;
            int n  = j * 8 + (lane >> 2);
            float p00 = W1[(k0 + 0) * 64 + n], p01 = W1[(k0 + 1) * 64 + n];
            float p10 = W1[(k0 + 8) * 64 + n], p11 = W1[(k0 + 9) * 64 + n];
            uint32_t h0 = pack_hi(p00, p01), h1 = pack_hi(p10, p11);
            g_W1fragHi[e] = make_uint2(h0, h1);
            g_W1fragLo[e] = make_uint2(pack_lo(p00, p01, h0), pack_lo(p10, p11, h1));
        }
        {   // W2 [64 x 32]: e = kt*128 + nt*32 + lane
            int kt = e >> 7, nt = (e >> 5) & 3;
            int k0 = kt * 16 + (lane & 3) * 2;
            int n  = nt * 8 + (lane >> 2);
            float p00 = W2[(k0 + 0) * 32 + n], p01 = W2[(k0 + 1) * 32 + n];
            float p10 = W2[(k0 + 8) * 32 + n], p11 = W2[(k0 + 9) * 32 + n];
            uint32_t h0 = pack_hi(p00, p01), h1 = pack_hi(p10, p11);
            g_W2fragHi[e] = make_uint2(h0, h1);
            g_W2fragLo[e] = make_uint2(pack_lo(p00, p01, h0), pack_lo(p10, p11, h1));
        }
    }
}

// ---------------- fused edge kernel (R11 structure) ----------------
__global__ void __launch_bounds__(256, 4)
edge_kernel(const int* __restrict__ ei,
            const float* __restrict__ b1,
            const float* __restrict__ b2,
            const float* __restrict__ W3,
            const float* __restrict__ b3,
            float* __restrict__ out,
            int E, int do_idx) {
    __shared__ __align__(16) unsigned char sAhi[EPB * APITCH];
    __shared__ __align__(16) unsigned char sAlo[EPB * APITCH];
    __shared__ __align__(16) uint2 sW1H[512], sW1L[512], sW2H[512], sW2L[512];
    __shared__ int sU[EPB], sV[EPB];
    __shared__ __align__(16) float sB1[64];
    __shared__ __align__(16) float sB2[32], sW3[32];
    __shared__ float sB3;

    const int tid = threadIdx.x;
    const int wid = tid >> 5, lid = tid & 31;
    const int q = lid & 3;

    for (int i = tid; i < 512; i += 256) {
        sW1H[i] = g_W1fragHi[i]; sW1L[i] = g_W1fragLo[i];
        sW2H[i] = g_W2fragHi[i]; sW2L[i] = g_W2fragLo[i];
    }
    if (tid < 64) sB1[tid] = b1[tid];
    if (tid < 32) { sB2[tid] = b2[tid]; sW3[tid] = W3[tid]; }
    if (tid == 0) sB3 = b3[0];

    const int base = blockIdx.x * EPB;
    const int nE = min(EPB, E - base);
    if (tid < EPB) {
        if (tid < nE) { sU[tid] = __ldg(ei + base + tid); sV[tid] = __ldg(ei + (size_t)E + base + tid); }
        else          { sU[tid] = 0; sV[tid] = 0; }
    }
    __syncthreads();

    // Gather pre-split embeddings: pure uint4 copy (no conversion work).
    // idx -> (le, which, half): 512 tasks over 256 threads x 2 iters.
#pragma unroll
    for (int i = 0; i < 2; i++) {
        int idx = i * 256 + tid;
        int le = idx >> 2;
        int which = (idx >> 1) & 1;
        int half = idx & 1;
        int node = which ? sV[le] : sU[le];
        uint4 hv = __ldg(g_EmbHi + (size_t)node * 2 + half);
        uint4 lv = __ldg(g_EmbLo + (size_t)node * 2 + half);
        uint32_t off = (uint32_t)le * APITCH + (uint32_t)which * 32 + (uint32_t)half * 16;
        *(uint4*)(sAhi + off) = hv;
        *(uint4*)(sAlo + off) = lv;
    }
    __syncthreads();

    // Load emb A fragments (2 k-tiles, hi+lo). Warp computes rows [r0, r0+16).
    const int r0 = wid * 16;
    const uint32_t abh = smem_u32(sAhi);
    const uint32_t abl = smem_u32(sAlo);
    const uint32_t rowoff = ((uint32_t)r0 + (uint32_t)(lid & 15)) * APITCH + ((uint32_t)(lid >> 4)) * 16;
    uint32_t eh[2][4], el[2][4];
    ldmatrix_x4(eh[0][0], eh[0][1], eh[0][2], eh[0][3], abh + rowoff);
    ldmatrix_x4(eh[1][0], eh[1][1], eh[1][2], eh[1][3], abh + rowoff + 32);
    ldmatrix_x4(el[0][0], el[0][1], el[0][2], el[0][3], abl + rowoff);
    ldmatrix_x4(el[1][0], el[1][1], el[1][2], el[1][3], abl + rowoff + 32);

    float acc2[4][4];
#pragma unroll
    for (int nt = 0; nt < 4; nt++)
#pragma unroll
        for (int r = 0; r < 4; r++) acc2[nt][r] = 0.0f;

#pragma unroll
    for (int t = 0; t < 4; t++) {
        // ---- layer1: n-tiles j = 2t, 2t+1 (K=32, 3-term split) ----
        float a1[4] = {0, 0, 0, 0}, a1b[4] = {0, 0, 0, 0};
        {
            int j = 2 * t;
            uint2 w0h = sW1H[j * 32 + lid],  w1h = sW1H[(8 + j) * 32 + lid];
            uint2 w0l = sW1L[j * 32 + lid],  w1l = sW1L[(8 + j) * 32 + lid];
            mma_bf16(a1, eh[0][0], eh[0][1], eh[0][2], eh[0][3], w0h.x, w0h.y);
            mma_bf16(a1, eh[1][0], eh[1][1], eh[1][2], eh[1][3], w1h.x, w1h.y);
            mma_bf16(a1, el[0][0], el[0][1], el[0][2], el[0][3], w0h.x, w0h.y);
            mma_bf16(a1, el[1][0], el[1][1], el[1][2], el[1][3], w1h.x, w1h.y);
            mma_bf16(a1, eh[0][0], eh[0][1], eh[0][2], eh[0][3], w0l.x, w0l.y);
            mma_bf16(a1, eh[1][0], eh[1][1], eh[1][2], eh[1][3], w1l.x, w1l.y);
        }
        {
            int j = 2 * t + 1;
            uint2 w0h = sW1H[j * 32 + lid],  w1h = sW1H[(8 + j) * 32 + lid];
            uint2 w0l = sW1L[j * 32 + lid],  w1l = sW1L[(8 + j) * 32 + lid];
            mma_bf16(a1b, eh[0][0], eh[0][1], eh[0][2], eh[0][3], w0h.x, w0h.y);
            mma_bf16(a1b, eh[1][0], eh[1][1], eh[1][2], eh[1][3], w1h.x, w1h.y);
            mma_bf16(a1b, el[0][0], el[0][1], el[0][2], el[0][3], w0h.x, w0h.y);
            mma_bf16(a1b, el[1][0], el[1][1], el[1][2], el[1][3], w1h.x, w1h.y);
            mma_bf16(a1b, eh[0][0], eh[0][1], eh[0][2], eh[0][3], w0l.x, w0l.y);
            mma_bf16(a1b, eh[1][0], eh[1][1], eh[1][2], eh[1][3], w1l.x, w1l.y);
        }

        // ---- bias + ReLU + re-split: layer1 C-frag == layer2 A-frag (k-tile t) ----
        int col0 = 16 * t + 2 * q;
        float2 ba = *(const float2*)(sB1 + col0);
        float2 bb = *(const float2*)(sB1 + col0 + 8);
        float h0 = fmaxf(a1[0]  + ba.x, 0.0f), h1 = fmaxf(a1[1]  + ba.y, 0.0f);
        float h2 = fmaxf(a1[2]  + ba.x, 0.0f), h3 = fmaxf(a1[3]  + ba.y, 0.0f);
        float g0 = fmaxf(a1b[0] + bb.x, 0.0f), g1 = fmaxf(a1b[1] + bb.y, 0.0f);
        float g2 = fmaxf(a1b[2] + bb.x, 0.0f), g3 = fmaxf(a1b[3] + bb.y, 0.0f);
        uint32_t a0h = pack_hi(h0, h1), a1h_ = pack_hi(h2, h3);
        uint32_t a2h = pack_hi(g0, g1), a3h = pack_hi(g2, g3);
        uint32_t a0l = pack_lo(h0, h1, a0h), a1l = pack_lo(h2, h3, a1h_);
        uint32_t a2l = pack_lo(g0, g1, a2h), a3l = pack_lo(g2, g3, a3h);

        // ---- layer2: accumulate k-tile t into all 4 n-tiles (3-term split) ----
#pragma unroll
        for (int nt = 0; nt < 4; nt++) {
            uint2 bh = sW2H[(t * 4 + nt) * 32 + lid];
            uint2 bl = sW2L[(t * 4 + nt) * 32 + lid];
            mma_bf16(acc2[nt], a0h, a1h_, a2h, a3h, bh.x, bh.y);
            mma_bf16(acc2[nt], a0l, a1l,  a2l, a3l, bh.x, bh.y);
            mma_bf16(acc2[nt], a0h, a1h_, a2h, a3h, bl.x, bl.y);
        }
    }

    // ---- register epilogue: layer3 dot in C-frag layout + quad reduction ----
    float zA = 0.0f, zB = 0.0f;
#pragma unroll
    for (int nt = 0; nt < 4; nt++) {
        float2 bb = *(const float2*)(sB2 + nt * 8 + 2 * q);
        float2 ww = *(const float2*)(sW3 + nt * 8 + 2 * q);
        zA = fmaf(fmaxf(acc2[nt][0] + bb.x, 0.0f), ww.x, zA);
        zA = fmaf(fmaxf(acc2[nt][1] + bb.y, 0.0f), ww.y, zA);
        zB = fmaf(fmaxf(acc2[nt][2] + bb.x, 0.0f), ww.x, zB);
        zB = fmaf(fmaxf(acc2[nt][3] + bb.y, 0.0f), ww.y, zB);
    }
    zA += __shfl_xor_sync(0xffffffffu, zA, 1);
    zA += __shfl_xor_sync(0xffffffffu, zA, 2);
    zB += __shfl_xor_sync(0xffffffffu, zB, 1);
    zB += __shfl_xor_sync(0xffffffffu, zB, 2);
    if (q == 0) {
        int rA = r0 + (lid >> 2);
        int rB = rA + 8;
        if (rA < nE) out[base + rA] = 1.0f / (1.0f + __expf(-(zA + sB3)));
        if (rB < nE) out[base + rB] = 1.0f / (1.0f + __expf(-(zB + sB3)));
    }

    // ---- edge_index passthrough (from staged indices, coalesced) ----
    if (do_idx) {
        if (tid < EPB) {
            if (tid < nE) out[(size_t)E + base + tid] = (float)sU[tid];
        } else {
            int t2 = tid - EPB;
            if (t2 < nE) out[(size_t)2 * E + base + t2] = (float)sV[t2];
        }
    }
}

extern "C" void kernel_launch(void* const* d_in, const int* in_sizes, int n_in,
                              void* d_out, int out_size) {
    const float* emb = (const float*)d_in[0];
    const int*   ei  = (const int*)d_in[1];
    const float* W1  = (const float*)d_in[2];
    const float* b1  = (const float*)d_in[3];
    const float* W2  = (const float*)d_in[4];
    const float* b2  = (const float*)d_in[5];
    const float* W3  = (const float*)d_in[6];
    const float* b3  = (const float*)d_in[7];

    int n_nodes = in_sizes[0] / 16;
    int E       = in_sizes[1] / 2;
    float* out  = (float*)d_out;
    int do_idx  = (out_size >= 3 * E) ? 1 : 0;

    prep_emb<<<(2 * n_nodes + 255) / 256, 256>>>(emb, n_nodes);
    prep_frags<<<1, 256>>>(W1, W2);
    edge_kernel<<<(E + EPB - 1) / EPB, 256>>>(ei, b1, b2, W3, b3, out, E, do_idx);
}

// round 17
// speedup vs baseline: 1.6060x; 1.2816x over previous
#include <cuda_runtime.h>
#include <cuda_fp16.h>
#include <cstdint>

// EdgeDecoder: probs = sigmoid(relu(relu(concat(emb[u],emb[v])@W1+b1)@W2+b2)@W3+b3)
// R11 structure (BEST at 348.8us): fused layer1 MMA -> in-register relu/resplit ->
//   layer2 MMA -> register epilogue (layer3 in C-frag layout + quad shfl).
// R17: 3-term bf16 -> 2-term fp16. A-side (emb, h1) split fp16 hi+lo (~21-bit),
//   B-side (W1, W2) single rounded fp16 (|W|<0.2, no range issue). MMAs 96->64
//   per warp-tile, W-frag LDS halved, third-term ALU deleted, smem -8KB.

#define EPB 128
#define APITCH 80        // A row pitch bytes (64B emb-pair data + 16 pad)

// Per-lane packed fp16 fragments: W1 [kt1(2)][j(8)][lane], W2 [kt(4)][nt(4)][lane]
__device__ __align__(16) uint2 g_W1frag[512];
__device__ __align__(16) uint2 g_W2frag[512];

__device__ __forceinline__ uint32_t smem_u32(const void* p) {
    uint32_t a;
    asm("{ .reg .u64 t; cvta.to.shared.u64 t, %1; cvt.u32.u64 %0, t; }" : "=r"(a) : "l"(p));
    return a;
}
__device__ __forceinline__ void ldmatrix_x4(uint32_t& a0, uint32_t& a1,
                                            uint32_t& a2, uint32_t& a3, uint32_t addr) {
    asm volatile("ldmatrix.sync.aligned.m8n8.x4.shared.b16 {%0,%1,%2,%3}, [%4];"
                 : "=r"(a0), "=r"(a1), "=r"(a2), "=r"(a3) : "r"(addr));
}
__device__ __forceinline__ void mma_f16(float* c, uint32_t a0, uint32_t a1,
                                        uint32_t a2, uint32_t a3,
                                        uint32_t b0, uint32_t b1) {
    asm volatile("mma.sync.aligned.m16n8k16.row.col.f32.f16.f16.f32 "
                 "{%0,%1,%2,%3},{%4,%5,%6,%7},{%8,%9},{%0,%1,%2,%3};"
                 : "+f"(c[0]), "+f"(c[1]), "+f"(c[2]), "+f"(c[3])
                 : "r"(a0), "r"(a1), "r"(a2), "r"(a3), "r"(b0), "r"(b1));
}
__device__ __forceinline__ uint32_t pack_h16(float a, float b) {
    __half2 h = __floats2half2_rn(a, b);
    return *(uint32_t*)&h;
}
__device__ __forceinline__ uint32_t pack_l16(float a, float b, uint32_t hi) {
    __half2 h = *(__half2*)&hi;
    __half2 l = __floats2half2_rn(a - __half2float(__low2half(h)),
                                  b - __half2float(__high2half(h)));
    return *(uint32_t*)&l;
}

// ---------------- prep: per-lane packed W1/W2 fp16 fragments ----------------
__global__ void __launch_bounds__(256)
prep_frags(const float* __restrict__ W1, const float* __restrict__ W2) {
    int tid = threadIdx.x;
    for (int e = tid; e < 512; e += 256) {
        int lane = e & 31;
        {   // W1 [32 x 64]: e = kt1*256 + j*32 + lane
            int kt1 = e >> 8, j = (e >> 5) & 7;
            int k0 = kt1 * 16 + (lane & 3) * 2;
            int n  = j * 8 + (lane >> 2);
            float p00 = W1[(k0 + 0) * 64 + n], p01 = W1[(k0 + 1) * 64 + n];
            float p10 = W1[(k0 + 8) * 64 + n], p11 = W1[(k0 + 9) * 64 + n];
            g_W1frag[e] = make_uint2(pack_h16(p00, p01), pack_h16(p10, p11));
        }
        {   // W2 [64 x 32]: e = kt*128 + nt*32 + lane
            int kt = e >> 7, nt = (e >> 5) & 3;
            int k0 = kt * 16 + (lane & 3) * 2;
            int n  = nt * 8 + (lane >> 2);
            float p00 = W2[(k0 + 0) * 32 + n], p01 = W2[(k0 + 1) * 32 + n];
            float p10 = W2[(k0 + 8) * 32 + n], p11 = W2[(k0 + 9) * 32 + n];
            g_W2frag[e] = make_uint2(pack_h16(p00, p01), pack_h16(p10, p11));
        }
    }
}

// ---------------- fused edge kernel (R11 structure, fp16 2-term) ----------------
__global__ void __launch_bounds__(256, 4)
edge_kernel(const float* __restrict__ emb,
            const int* __restrict__ ei,
            const float* __restrict__ b1,
            const float* __restrict__ b2,
            const float* __restrict__ W3,
            const float* __restrict__ b3,
            float* __restrict__ out,
            int E, int do_idx) {
    __shared__ __align__(16) unsigned char sAhi[EPB * APITCH];
    __shared__ __align__(16) unsigned char sAlo[EPB * APITCH];
    __shared__ __align__(16) uint2 sW1[512], sW2[512];
    __shared__ int sU[EPB], sV[EPB];
    __shared__ __align__(16) float sB1[64];
    __shared__ __align__(16) float sB2[32], sW3[32];
    __shared__ float sB3;

    const int tid = threadIdx.x;
    const int wid = tid >> 5, lid = tid & 31;
    const int q = lid & 3;

    for (int i = tid; i < 512; i += 256) { sW1[i] = g_W1frag[i]; sW2[i] = g_W2frag[i]; }
    if (tid < 64) sB1[tid] = b1[tid];
    if (tid < 32) { sB2[tid] = b2[tid]; sW3[tid] = W3[tid]; }
    if (tid == 0) sB3 = b3[0];

    const int base = blockIdx.x * EPB;
    const int nE = min(EPB, E - base);
    if (tid < EPB) {
        if (tid < nE) { sU[tid] = __ldg(ei + base + tid); sV[tid] = __ldg(ei + (size_t)E + base + tid); }
        else          { sU[tid] = 0; sV[tid] = 0; }
    }
    __syncthreads();

    // Gather raw embeddings: 4 lanes per node row (64B). Split to fp16 hi/lo.
#pragma unroll
    for (int i = 0; i < 4; i++) {
        int idx = i * 256 + tid;
        int le = idx >> 3;
        int which = (idx >> 2) & 1;
        int s = idx & 3;
        int node = which ? sV[le] : sU[le];
        float4 v = __ldg((const float4*)(emb + (size_t)node * 16) + s);
        uint32_t h01 = pack_h16(v.x, v.y), h23 = pack_h16(v.z, v.w);
        uint32_t l01 = pack_l16(v.x, v.y, h01), l23 = pack_l16(v.z, v.w, h23);
        uint32_t off = (uint32_t)le * APITCH + (uint32_t)which * 32 + (uint32_t)s * 8;
        *(uint2*)(sAhi + off) = make_uint2(h01, h23);
        *(uint2*)(sAlo + off) = make_uint2(l01, l23);
    }
    __syncthreads();

    // Load emb A fragments (2 k-tiles, hi+lo). Warp computes rows [r0, r0+16).
    const int r0 = wid * 16;
    const uint32_t abh = smem_u32(sAhi);
    const uint32_t abl = smem_u32(sAlo);
    const uint32_t rowoff = ((uint32_t)r0 + (uint32_t)(lid & 15)) * APITCH + ((uint32_t)(lid >> 4)) * 16;
    uint32_t eh[2][4], el[2][4];
    ldmatrix_x4(eh[0][0], eh[0][1], eh[0][2], eh[0][3], abh + rowoff);
    ldmatrix_x4(eh[1][0], eh[1][1], eh[1][2], eh[1][3], abh + rowoff + 32);
    ldmatrix_x4(el[0][0], el[0][1], el[0][2], el[0][3], abl + rowoff);
    ldmatrix_x4(el[1][0], el[1][1], el[1][2], el[1][3], abl + rowoff + 32);

    float acc2[4][4];
#pragma unroll
    for (int nt = 0; nt < 4; nt++)
#pragma unroll
        for (int r = 0; r < 4; r++) acc2[nt][r] = 0.0f;

#pragma unroll
    for (int t = 0; t < 4; t++) {
        // ---- layer1: n-tiles j = 2t, 2t+1 (K=32, A 2-term fp16, B single fp16) ----
        float a1[4] = {0, 0, 0, 0}, a1b[4] = {0, 0, 0, 0};
        {
            int j = 2 * t;
            uint2 w0 = sW1[j * 32 + lid], w1 = sW1[(8 + j) * 32 + lid];
            mma_f16(a1, eh[0][0], eh[0][1], eh[0][2], eh[0][3], w0.x, w0.y);
            mma_f16(a1, eh[1][0], eh[1][1], eh[1][2], eh[1][3], w1.x, w1.y);
            mma_f16(a1, el[0][0], el[0][1], el[0][2], el[0][3], w0.x, w0.y);
            mma_f16(a1, el[1][0], el[1][1], el[1][2], el[1][3], w1.x, w1.y);
        }
        {
            int j = 2 * t + 1;
            uint2 w0 = sW1[j * 32 + lid], w1 = sW1[(8 + j) * 32 + lid];
            mma_f16(a1b, eh[0][0], eh[0][1], eh[0][2], eh[0][3], w0.x, w0.y);
            mma_f16(a1b, eh[1][0], eh[1][1], eh[1][2], eh[1][3], w1.x, w1.y);
            mma_f16(a1b, el[0][0], el[0][1], el[0][2], el[0][3], w0.x, w0.y);
            mma_f16(a1b, el[1][0], el[1][1], el[1][2], el[1][3], w1.x, w1.y);
        }

        // ---- bias + ReLU + fp16 re-split: layer1 C-frag == layer2 A-frag ----
        int col0 = 16 * t + 2 * q;
        float2 ba = *(const float2*)(sB1 + col0);
        float2 bb = *(const float2*)(sB1 + col0 + 8);
        float h0 = fmaxf(a1[0]  + ba.x, 0.0f), h1 = fmaxf(a1[1]  + ba.y, 0.0f);
        float h2 = fmaxf(a1[2]  + ba.x, 0.0f), h3 = fmaxf(a1[3]  + ba.y, 0.0f);
        float g0 = fmaxf(a1b[0] + bb.x, 0.0f), g1 = fmaxf(a1b[1] + bb.y, 0.0f);
        float g2 = fmaxf(a1b[2] + bb.x, 0.0f), g3 = fmaxf(a1b[3] + bb.y, 0.0f);
        uint32_t a0h = pack_h16(h0, h1), a1h_ = pack_h16(h2, h3);
        uint32_t a2h = pack_h16(g0, g1), a3h = pack_h16(g2, g3);
        uint32_t a0l = pack_l16(h0, h1, a0h), a1l = pack_l16(h2, h3, a1h_);
        uint32_t a2l = pack_l16(g0, g1, a2h), a3l = pack_l16(g2, g3, a3h);

        // ---- layer2: k-tile t into all 4 n-tiles (A 2-term, B single fp16) ----
#pragma unroll
        for (int nt = 0; nt < 4; nt++) {
            uint2 b = sW2[(t * 4 + nt) * 32 + lid];
            mma_f16(acc2[nt], a0h, a1h_, a2h, a3h, b.x, b.y);
            mma_f16(acc2[nt], a0l, a1l,  a2l, a3l, b.x, b.y);
        }
    }

    // ---- register epilogue: layer3 dot in C-frag layout + quad reduction ----
    float zA = 0.0f, zB = 0.0f;
#pragma unroll
    for (int nt = 0; nt < 4; nt++) {
        float2 bb = *(const float2*)(sB2 + nt * 8 + 2 * q);
        float2 ww = *(const float2*)(sW3 + nt * 8 + 2 * q);
        zA = fmaf(fmaxf(acc2[nt][0] + bb.x, 0.0f), ww.x, zA);
        zA = fmaf(fmaxf(acc2[nt][1] + bb.y, 0.0f), ww.y, zA);
        zB = fmaf(fmaxf(acc2[nt][2] + bb.x, 0.0f), ww.x, zB);
        zB = fmaf(fmaxf(acc2[nt][3] + bb.y, 0.0f), ww.y, zB);
    }
    zA += __shfl_xor_sync(0xffffffffu, zA, 1);
    zA += __shfl_xor_sync(0xffffffffu, zA, 2);
    zB += __shfl_xor_sync(0xffffffffu, zB, 1);
    zB += __shfl_xor_sync(0xffffffffu, zB, 2);
    if (q == 0) {
        int rA = r0 + (lid >> 2);
        int rB = rA + 8;
        if (rA < nE) out[base + rA] = 1.0f / (1.0f + __expf(-(zA + sB3)));
        if (rB < nE) out[base + rB] = 1.0f / (1.0f + __expf(-(zB + sB3)));
    }

    // ---- edge_index passthrough (from staged indices, coalesced) ----
    if (do_idx) {
        if (tid < EPB) {
            if (tid < nE) out[(size_t)E + base + tid] = (float)sU[tid];
        } else {
            int t2 = tid - EPB;
            if (t2 < nE) out[(size_t)2 * E + base + t2] = (float)sV[t2];
        }
    }
}

extern "C" void kernel_launch(void* const* d_in, const int* in_sizes, int n_in,
                              void* d_out, int out_size) {
    const float* emb = (const float*)d_in[0];
    const int*   ei  = (const int*)d_in[1];
    const float* W1  = (const float*)d_in[2];
    const float* b1  = (const float*)d_in[3];
    const float* W2  = (const float*)d_in[4];
    const float* b2  = (const float*)d_in[5];
    const float* W3  = (const float*)d_in[6];
    const float* b3  = (const float*)d_in[7];

    int E      = in_sizes[1] / 2;
    float* out = (float*)d_out;
    int do_idx = (out_size >= 3 * E) ? 1 : 0;

    prep_frags<<<1, 256>>>(W1, W2);
    edge_kernel<<<(E + EPB - 1) / EPB, 256>>>(emb, ei, b1, b2, W3, b3, out, E, do_idx);
}